// round 1
// baseline (speedup 1.0000x reference)
#include <cuda_runtime.h>
#include <cstdint>

typedef unsigned long long u64;
typedef unsigned int u32;

#define NMAX      250048
#define PRE_NMS   6000
#define POST_NMS  300
#define CAP       32768
#define WORDS     94            // ceil(6000/64)
#define IOU_THR   0.7f
#define IMG_H     1024.0f
#define IMG_W     1024.0f
#define STRIDE_F  16.0f
#define DEPTH     8

// ---------------- device scratch (static, allocation-free) ----------------
__device__ u32   g_hist[65536];
__device__ u32   g_t16;
__device__ u32   g_candCount;
__device__ u64   g_keys[NMAX];
__device__ float4 g_boxes[NMAX];
__device__ u64   g_cand[CAP];
__device__ float4 g_sortedBoxes[PRE_NMS + 64];
__device__ __align__(16) u64 g_mask[(size_t)PRE_NMS * WORDS];

// ---------------- helpers ----------------
__device__ __forceinline__ u32 flip_score(float s) {
    u32 u = __float_as_uint(s);
    return (u & 0x80000000u) ? ~u : (u | 0x80000000u);
}

__device__ __forceinline__ void cp_async16(void* smem, const void* gmem) {
    u32 s = (u32)__cvta_generic_to_shared(smem);
    asm volatile("cp.async.ca.shared.global [%0], [%1], 16;\n" :: "r"(s), "l"(gmem));
}

// ---------------- K0: zero scratch + output ----------------
__global__ void k0_zero(float* out) {
    int i = blockIdx.x * 256 + threadIdx.x;
    if (i < 65536) g_hist[i] = 0u;
    if (i < POST_NMS * 4) out[i] = 0.0f;
    if (i == 0) g_candCount = 0u;
}

// ---------------- K1: decode + clip + valid + key + 16-bit histogram ----------------
__global__ void k1_decode(const float* __restrict__ deltas,
                          const float* __restrict__ anchors,
                          const float* __restrict__ scores, int N) {
    int i = blockIdx.x * 256 + threadIdx.x;
    if (i >= N) return;
    float4 a = reinterpret_cast<const float4*>(anchors)[i];
    float4 d = reinterpret_cast<const float4*>(deltas)[i];
    float h = a.z - a.x;
    float w = a.w - a.y;
    float cy = a.x + 0.5f * h;
    float cx = a.y + 0.5f * w;
    float ncy = d.x * h + cy;
    float ncx = d.y * w + cx;
    float nh = expf(d.z) * h;
    float nw = expf(d.w) * w;
    float ymin = fminf(fmaxf(ncy - 0.5f * nh, 0.0f), IMG_H);
    float xmin = fminf(fmaxf(ncx - 0.5f * nw, 0.0f), IMG_W);
    float ymax = fminf(fmaxf(ncy + 0.5f * nh, 0.0f), IMG_H);
    float xmax = fminf(fmaxf(ncx + 0.5f * nw, 0.0f), IMG_W);
    g_boxes[i] = make_float4(ymin, xmin, ymax, xmax);
    bool valid = ((ymax - ymin) >= STRIDE_F) && ((xmax - xmin) >= STRIDE_F);
    u64 key = 0ull;
    if (valid) {
        u32 u = flip_score(scores[i]);
        key = ((u64)u << 32) | (u32)(~(u32)i);
        atomicAdd(&g_hist[u >> 16], 1u);
    }
    g_keys[i] = key;
}

// ---------------- K2: find 16-bit threshold so that count(prefix >= t) >= 6000 ----------------
__global__ void k2_threshold() {
    __shared__ u32 ssum[1024];
    int t = threadIdx.x;
    u32 sum = 0;
    #pragma unroll 8
    for (int b = 0; b < 64; b++) sum += g_hist[(t << 6) + b];
    ssum[t] = sum;
    __syncthreads();
    // inclusive suffix scan (Hillis-Steele)
    for (int off = 1; off < 1024; off <<= 1) {
        u32 v = (t + off < 1024) ? ssum[t + off] : 0u;
        __syncthreads();
        ssum[t] += v;
        __syncthreads();
    }
    u32 myCum = ssum[t];
    u32 nxtCum = (t < 1023) ? ssum[t + 1] : 0u;
    if (myCum >= PRE_NMS && nxtCum < PRE_NMS) {
        u32 running = nxtCum;
        for (int b = 63; b >= 0; b--) {
            running += g_hist[(t << 6) + b];
            if (running >= PRE_NMS) { g_t16 = (u32)((t << 6) + b); break; }
        }
    }
    if (t == 0 && ssum[0] < PRE_NMS) g_t16 = 0u;   // fewer than 6000 valid
}

// ---------------- K3: compact candidates (prefix >= t16) ----------------
__global__ void k3_compact(int N) {
    int i = blockIdx.x * 256 + threadIdx.x;
    if (i >= N) return;
    u64 key = g_keys[i];
    if (key != 0ull && (u32)(key >> 48) >= g_t16) {
        u32 pos = atomicAdd(&g_candCount, 1u);
        if (pos < CAP) g_cand[pos] = key;
    }
}

// ---------------- K4: exact rank by counting -> sorted boxes ----------------
__global__ void k4_rank() {
    int C = min((int)g_candCount, CAP);
    int i = blockIdx.x * 256 + threadIdx.x;
    if (blockIdx.x * 256 >= C) return;
    u64 myKey = (i < C) ? g_cand[i] : 0ull;
    __shared__ u64 tile[256];
    int cnt = 0;
    for (int base = 0; base < C; base += 256) {
        if (base + threadIdx.x < C) tile[threadIdx.x] = g_cand[base + threadIdx.x];
        __syncthreads();
        int m = min(256, C - base);
        int k = 0;
        for (; k + 4 <= m; k += 4) {
            cnt += (tile[k]   > myKey);
            cnt += (tile[k+1] > myKey);
            cnt += (tile[k+2] > myKey);
            cnt += (tile[k+3] > myKey);
        }
        for (; k < m; k++) cnt += (tile[k] > myKey);
        __syncthreads();
    }
    if (i < C && cnt < PRE_NMS) {
        u32 idx = ~(u32)(myKey & 0xFFFFFFFFull);
        g_sortedBoxes[cnt] = g_boxes[idx];
    }
}

// ---------------- K5: suppression bitmask (j > i, IoU > 0.7) ----------------
// dynamic smem: 6016 float4 boxes + 6016 float areas = 120320 B
__global__ void k5_mask() {
    extern __shared__ char sm5[];
    float4* sBox  = (float4*)sm5;
    float*  sArea = (float*)(sm5 + 6016 * sizeof(float4));
    int n = min((int)g_candCount, PRE_NMS);
    for (int j = threadIdx.x; j < 6016; j += 256) {
        float4 b = (j < n) ? g_sortedBoxes[j] : make_float4(0.f, 0.f, 0.f, 0.f);
        sBox[j] = b;
        sArea[j] = (b.z - b.x) * (b.w - b.y);
    }
    __syncthreads();
    // p = w*64 + r : lanes in a warp share word w -> bj loads broadcast
    for (int p = threadIdx.x; p < WORDS * 64; p += 256) {
        int w = p >> 6;
        int r = p & 63;
        int i = blockIdx.x + WORDS * r;   // interleaved rows for load balance
        if (i >= PRE_NMS) continue;
        u64 word = 0ull;
        int j0 = w << 6;
        if (i < n && (j0 + 63) > i) {
            float4 bi = sBox[i];
            float   ai = sArea[i];
            #pragma unroll 8
            for (int b = 0; b < 64; b++) {
                int j = j0 + b;
                float4 bj = sBox[j];
                float  aj = sArea[j];
                float iy = fmaxf(0.0f, fminf(bi.z, bj.z) - fmaxf(bi.x, bj.x));
                float ix = fmaxf(0.0f, fminf(bi.w, bj.w) - fmaxf(bi.y, bj.y));
                float inter = iy * ix;
                float iou = inter / (ai + aj - inter + 1e-9f);
                if (iou > IOU_THR && j > i) word |= (1ull << b);
            }
        }
        g_mask[(size_t)i * WORDS + w] = word;
    }
}

// ---------------- K6: serial greedy NMS with cp.async row prefetch, early exit at 300 kept ----------------
__global__ void k6_nms(float* __restrict__ out) {
    __shared__ u64 removed[WORDS];
    __shared__ __align__(16) u64 ring[DEPTH][WORDS];
    int t = threadIdx.x;   // 128 threads
    int n = min((int)g_candCount, PRE_NMS);
    if (t < WORDS) removed[t] = 0ull;
    // prologue: prefetch rows 0..DEPTH-1
    for (int d = 0; d < DEPTH; d++) {
        if (d < n && t < 47)
            cp_async16(&ring[d][t * 2], &g_mask[(size_t)d * WORDS + t * 2]);
        asm volatile("cp.async.commit_group;\n");
    }
    int kept = 0;
    for (int i = 0; i < n; i++) {
        asm volatile("cp.async.wait_group %0;\n" :: "n"(DEPTH - 1));
        __syncthreads();
        bool alive = ((removed[i >> 6] >> (i & 63)) & 1ull) == 0ull;
        if (alive) {
            if (t < WORDS) removed[t] |= ring[i & (DEPTH - 1)][t];
            if (t == 0) reinterpret_cast<float4*>(out)[kept] = g_sortedBoxes[i];
            kept++;
            if (kept >= POST_NMS) break;
        }
        __syncthreads();
        int nx = i + DEPTH;
        if (nx < n && t < 47)
            cp_async16(&ring[nx & (DEPTH - 1)][t * 2], &g_mask[(size_t)nx * WORDS + t * 2]);
        asm volatile("cp.async.commit_group;\n");
    }
    asm volatile("cp.async.wait_group 0;\n");
}

// ---------------- launch ----------------
extern "C" void kernel_launch(void* const* d_in, const int* in_sizes, int n_in,
                              void* d_out, int out_size) {
    const float* deltas  = (const float*)d_in[0];
    const float* anchors = (const float*)d_in[1];
    const float* scores  = (const float*)d_in[2];
    int N = in_sizes[2];
    if (N > NMAX) N = NMAX;
    float* out = (float*)d_out;

    k0_zero<<<256, 256>>>(out);
    k1_decode<<<(N + 255) / 256, 256>>>(deltas, anchors, scores, N);
    k2_threshold<<<1, 1024>>>();
    k3_compact<<<(N + 255) / 256, 256>>>(N);
    k4_rank<<<CAP / 256, 256>>>();
    static const int SMEM5 = 6016 * (int)sizeof(float4) + 6016 * (int)sizeof(float);
    cudaFuncSetAttribute(k5_mask, cudaFuncAttributeMaxDynamicSharedMemorySize, SMEM5);
    k5_mask<<<WORDS, 256, SMEM5>>>();
    k6_nms<<<1, 128>>>(out);
}

// round 2
// speedup vs baseline: 1.7970x; 1.7970x over previous
#include <cuda_runtime.h>
#include <cstdint>

typedef unsigned long long u64;
typedef unsigned int u32;

#define NMAX      250048
#define PRE_NMS   6000
#define POST_NMS  300
#define CAP       32768
#define IOU_THR   0.7f
#define IMG_H     1024.0f
#define IMG_W     1024.0f
#define STRIDE_F  16.0f

// ---------------- device scratch (static, allocation-free) ----------------
__device__ u32    g_hist[65536];
__device__ u32    g_t16;
__device__ u32    g_candCount;
__device__ u64    g_keys[NMAX];
__device__ float4 g_boxes[NMAX];
__device__ u64    g_cand[CAP];
__device__ float4 g_sortedBoxes[PRE_NMS + 64];

// ---------------- helpers ----------------
__device__ __forceinline__ u32 flip_score(float s) {
    u32 u = __float_as_uint(s);
    return (u & 0x80000000u) ? ~u : (u | 0x80000000u);
}

// ---------------- K0: zero scratch + output ----------------
__global__ void k0_zero(float* out) {
    int i = blockIdx.x * 256 + threadIdx.x;
    if (i < 65536) g_hist[i] = 0u;
    if (i < POST_NMS * 4) out[i] = 0.0f;
    if (i == 0) g_candCount = 0u;
}

// ---------------- K1: decode + clip + valid + key + 16-bit histogram ----------------
__global__ void k1_decode(const float* __restrict__ deltas,
                          const float* __restrict__ anchors,
                          const float* __restrict__ scores, int N) {
    int i = blockIdx.x * 256 + threadIdx.x;
    if (i >= N) return;
    float4 a = reinterpret_cast<const float4*>(anchors)[i];
    float4 d = reinterpret_cast<const float4*>(deltas)[i];
    float h = a.z - a.x;
    float w = a.w - a.y;
    float cy = a.x + 0.5f * h;
    float cx = a.y + 0.5f * w;
    float ncy = d.x * h + cy;
    float ncx = d.y * w + cx;
    float nh = expf(d.z) * h;
    float nw = expf(d.w) * w;
    float ymin = fminf(fmaxf(ncy - 0.5f * nh, 0.0f), IMG_H);
    float xmin = fminf(fmaxf(ncx - 0.5f * nw, 0.0f), IMG_W);
    float ymax = fminf(fmaxf(ncy + 0.5f * nh, 0.0f), IMG_H);
    float xmax = fminf(fmaxf(ncx + 0.5f * nw, 0.0f), IMG_W);
    g_boxes[i] = make_float4(ymin, xmin, ymax, xmax);
    bool valid = ((ymax - ymin) >= STRIDE_F) && ((xmax - xmin) >= STRIDE_F);
    u64 key = 0ull;
    if (valid) {
        u32 u = flip_score(scores[i]);
        key = ((u64)u << 32) | (u32)(~(u32)i);
        atomicAdd(&g_hist[u >> 16], 1u);
    }
    g_keys[i] = key;
}

// ---------------- K2: find 16-bit threshold so that count(prefix >= t) >= 6000 ----------------
__global__ void k2_threshold() {
    __shared__ u32 ssum[1024];
    int t = threadIdx.x;
    u32 sum = 0;
    #pragma unroll 8
    for (int b = 0; b < 64; b++) sum += g_hist[(t << 6) + b];
    ssum[t] = sum;
    __syncthreads();
    // inclusive suffix scan (Hillis-Steele)
    for (int off = 1; off < 1024; off <<= 1) {
        u32 v = (t + off < 1024) ? ssum[t + off] : 0u;
        __syncthreads();
        ssum[t] += v;
        __syncthreads();
    }
    u32 myCum = ssum[t];
    u32 nxtCum = (t < 1023) ? ssum[t + 1] : 0u;
    if (myCum >= PRE_NMS && nxtCum < PRE_NMS) {
        u32 running = nxtCum;
        for (int b = 63; b >= 0; b--) {
            running += g_hist[(t << 6) + b];
            if (running >= PRE_NMS) { g_t16 = (u32)((t << 6) + b); break; }
        }
    }
    if (t == 0 && ssum[0] < PRE_NMS) g_t16 = 0u;   // fewer than 6000 valid
}

// ---------------- K3: compact candidates (prefix >= t16) ----------------
__global__ void k3_compact(int N) {
    int i = blockIdx.x * 256 + threadIdx.x;
    if (i >= N) return;
    u64 key = g_keys[i];
    if (key != 0ull && (u32)(key >> 48) >= g_t16) {
        u32 pos = atomicAdd(&g_candCount, 1u);
        if (pos < CAP) g_cand[pos] = key;
    }
}

// ---------------- K4: exact rank by counting -> sorted boxes ----------------
__global__ void k4_rank() {
    int C = min((int)g_candCount, CAP);
    int i = blockIdx.x * 256 + threadIdx.x;
    if (blockIdx.x * 256 >= C) return;
    u64 myKey = (i < C) ? g_cand[i] : 0ull;
    __shared__ u64 tile[256];
    int cnt = 0;
    for (int base = 0; base < C; base += 256) {
        if (base + threadIdx.x < C) tile[threadIdx.x] = g_cand[base + threadIdx.x];
        __syncthreads();
        int m = min(256, C - base);
        int k = 0;
        for (; k + 4 <= m; k += 4) {
            cnt += (tile[k]   > myKey);
            cnt += (tile[k+1] > myKey);
            cnt += (tile[k+2] > myKey);
            cnt += (tile[k+3] > myKey);
        }
        for (; k < m; k++) cnt += (tile[k] > myKey);
        __syncthreads();
    }
    if (i < C && cnt < PRE_NMS) {
        u32 idx = ~(u32)(myKey & 0xFFFFFFFFull);
        g_sortedBoxes[cnt] = g_boxes[idx];
    }
}

// ---------------- K5: fused incremental greedy NMS ----------------
// Candidate i (score order) is tested ONLY against already-kept boxes (<=300).
// Equivalent to the reference suppression recurrence; avoids the 6000x6000 mask.
// dynamic smem: 6000 cand float4 + 304 kept float4 + 304 kept areas
__global__ void k5_nms(float* __restrict__ out) {
    extern __shared__ char sm[];
    float4* cand  = (float4*)sm;                                 // 6000
    float4* kb    = (float4*)(sm + PRE_NMS * sizeof(float4));    // 304
    float*  karea = (float*)(sm + (PRE_NMS + 304) * sizeof(float4));
    int t = threadIdx.x;   // 256 threads
    int n = min((int)g_candCount, PRE_NMS);
    for (int j = t; j < n; j += 256) cand[j] = g_sortedBoxes[j];
    __syncthreads();

    int kept = 0;
    for (int i = 0; i < n; i++) {
        float4 b = cand[i];
        float  ab = (b.z - b.x) * (b.w - b.y);
        bool sup = false;
        for (int k = t; k < kept; k += 256) {
            float4 c  = kb[k];
            float  ac = karea[k];
            float iy = fmaxf(0.0f, fminf(b.z, c.z) - fmaxf(b.x, c.x));
            float ix = fmaxf(0.0f, fminf(b.w, c.w) - fmaxf(b.y, c.y));
            float inter = iy * ix;
            float iou = inter / (ab + ac - inter + 1e-9f);
            sup = sup || (iou > IOU_THR);
        }
        int any = __syncthreads_or((int)sup);   // uniform result + barrier
        if (!any) {
            if (t == 0) {
                kb[kept]    = b;
                karea[kept] = ab;
                reinterpret_cast<float4*>(out)[kept] = b;
            }
            kept++;
            if (kept >= POST_NMS) break;
            __syncthreads();   // order kb/karea write before next iteration's reads
        }
    }
}

// ---------------- launch ----------------
extern "C" void kernel_launch(void* const* d_in, const int* in_sizes, int n_in,
                              void* d_out, int out_size) {
    const float* deltas  = (const float*)d_in[0];
    const float* anchors = (const float*)d_in[1];
    const float* scores  = (const float*)d_in[2];
    int N = in_sizes[2];
    if (N > NMAX) N = NMAX;
    float* out = (float*)d_out;

    k0_zero<<<256, 256>>>(out);
    k1_decode<<<(N + 255) / 256, 256>>>(deltas, anchors, scores, N);
    k2_threshold<<<1, 1024>>>();
    k3_compact<<<(N + 255) / 256, 256>>>(N);
    k4_rank<<<CAP / 256, 256>>>();
    static const int SMEM5 = (PRE_NMS + 304) * (int)sizeof(float4) + 304 * (int)sizeof(float);
    cudaFuncSetAttribute(k5_nms, cudaFuncAttributeMaxDynamicSharedMemorySize, SMEM5);
    k5_nms<<<1, 256, SMEM5>>>(out);
}

// round 3
// speedup vs baseline: 2.8386x; 1.5796x over previous
#include <cuda_runtime.h>
#include <cstdint>

typedef unsigned long long u64;
typedef unsigned int u32;

#define NMAX      250048
#define PRE_NMS   6000
#define POST_NMS  300
#define CAP       32768
#define IOU_THR   0.7f
#define IMG_H     1024.0f
#define IMG_W     1024.0f
#define STRIDE_F  16.0f
#define MCH       1024          // fast-path chunk for NMS bitmask
#define MWORDS    16            // 1024/64

// ---------------- device scratch (static, allocation-free) ----------------
__device__ u32    g_hist[65536];
__device__ u32    g_t16;
__device__ u32    g_candCount;
__device__ u64    g_keys[NMAX];
__device__ float4 g_boxes[NMAX];
__device__ u64    g_cand[CAP];
__device__ float4 g_sortedBoxes[PRE_NMS + 64];
__device__ __align__(16) u64 g_mask1024[MCH * MWORDS];

// ---------------- helpers ----------------
__device__ __forceinline__ u32 flip_score(float s) {
    u32 u = __float_as_uint(s);
    return (u & 0x80000000u) ? ~u : (u | 0x80000000u);
}

// ---------------- K0: zero scratch + output ----------------
__global__ void k0_zero(float* out) {
    int i = blockIdx.x * 256 + threadIdx.x;
    if (i < 65536) g_hist[i] = 0u;
    if (i < POST_NMS * 4) out[i] = 0.0f;
    if (i == 0) g_candCount = 0u;
}

// ---------------- K1: decode + clip + valid + key + 16-bit histogram ----------------
__global__ void k1_decode(const float* __restrict__ deltas,
                          const float* __restrict__ anchors,
                          const float* __restrict__ scores, int N) {
    int i = blockIdx.x * 256 + threadIdx.x;
    if (i >= N) return;
    float4 a = reinterpret_cast<const float4*>(anchors)[i];
    float4 d = reinterpret_cast<const float4*>(deltas)[i];
    float h = a.z - a.x;
    float w = a.w - a.y;
    float cy = a.x + 0.5f * h;
    float cx = a.y + 0.5f * w;
    float ncy = d.x * h + cy;
    float ncx = d.y * w + cx;
    float nh = expf(d.z) * h;
    float nw = expf(d.w) * w;
    float ymin = fminf(fmaxf(ncy - 0.5f * nh, 0.0f), IMG_H);
    float xmin = fminf(fmaxf(ncx - 0.5f * nw, 0.0f), IMG_W);
    float ymax = fminf(fmaxf(ncy + 0.5f * nh, 0.0f), IMG_H);
    float xmax = fminf(fmaxf(ncx + 0.5f * nw, 0.0f), IMG_W);
    g_boxes[i] = make_float4(ymin, xmin, ymax, xmax);
    bool valid = ((ymax - ymin) >= STRIDE_F) && ((xmax - xmin) >= STRIDE_F);
    u64 key = 0ull;
    if (valid) {
        u32 u = flip_score(scores[i]);
        key = ((u64)u << 32) | (u32)(~(u32)i);
        atomicAdd(&g_hist[u >> 16], 1u);
    }
    g_keys[i] = key;
}

// ---------------- K2: find 16-bit threshold so that count(prefix >= t) >= 6000 ----------------
__global__ void k2_threshold() {
    __shared__ u32 ssum[1024];
    int t = threadIdx.x;
    u32 sum = 0;
    #pragma unroll 8
    for (int b = 0; b < 64; b++) sum += g_hist[(t << 6) + b];
    ssum[t] = sum;
    __syncthreads();
    for (int off = 1; off < 1024; off <<= 1) {
        u32 v = (t + off < 1024) ? ssum[t + off] : 0u;
        __syncthreads();
        ssum[t] += v;
        __syncthreads();
    }
    u32 myCum = ssum[t];
    u32 nxtCum = (t < 1023) ? ssum[t + 1] : 0u;
    if (myCum >= PRE_NMS && nxtCum < PRE_NMS) {
        u32 running = nxtCum;
        for (int b = 63; b >= 0; b--) {
            running += g_hist[(t << 6) + b];
            if (running >= PRE_NMS) { g_t16 = (u32)((t << 6) + b); break; }
        }
    }
    if (t == 0 && ssum[0] < PRE_NMS) g_t16 = 0u;
}

// ---------------- K3: compact candidates (prefix >= t16) ----------------
__global__ void k3_compact(int N) {
    int i = blockIdx.x * 256 + threadIdx.x;
    if (i >= N) return;
    u64 key = g_keys[i];
    if (key != 0ull && (u32)(key >> 48) >= g_t16) {
        u32 pos = atomicAdd(&g_candCount, 1u);
        if (pos < CAP) g_cand[pos] = key;
    }
}

// ---------------- K4: exact rank by counting -> sorted boxes ----------------
__global__ void k4_rank() {
    int C = min((int)g_candCount, CAP);
    int i = blockIdx.x * 256 + threadIdx.x;
    if (blockIdx.x * 256 >= C) return;
    u64 myKey = (i < C) ? g_cand[i] : 0ull;
    __shared__ u64 tile[256];
    int cnt = 0;
    for (int base = 0; base < C; base += 256) {
        if (base + threadIdx.x < C) tile[threadIdx.x] = g_cand[base + threadIdx.x];
        __syncthreads();
        int m = min(256, C - base);
        int k = 0;
        for (; k + 4 <= m; k += 4) {
            cnt += (tile[k]   > myKey);
            cnt += (tile[k+1] > myKey);
            cnt += (tile[k+2] > myKey);
            cnt += (tile[k+3] > myKey);
        }
        for (; k < m; k++) cnt += (tile[k] > myKey);
        __syncthreads();
    }
    if (i < C && cnt < PRE_NMS) {
        u32 idx = ~(u32)(myKey & 0xFFFFFFFFull);
        g_sortedBoxes[cnt] = g_boxes[idx];
    }
}

// ---------------- K5a: suppression bitmask over first 1024 candidates ----------------
// grid 64 x 256: thread (r = tid&15, w = tid>>4) -> row i = blk*16 + r, word w.
// Lanes sharing w read the same sBox[j] -> smem broadcast.
__global__ void k5a_mask() {
    __shared__ float4 sBox[MCH];
    __shared__ float  sArea[MCH];
    int n = min((int)g_candCount, PRE_NMS);
    for (int j = threadIdx.x; j < MCH; j += 256) {
        float4 b = (j < n) ? g_sortedBoxes[j] : make_float4(0.f, 0.f, 0.f, 0.f);
        sBox[j] = b;
        sArea[j] = (b.z - b.x) * (b.w - b.y);
    }
    __syncthreads();
    int r = threadIdx.x & 15;
    int w = threadIdx.x >> 4;
    int i = blockIdx.x * 16 + r;
    u64 word = 0ull;
    int j0 = w << 6;
    if (i < n && (j0 + 63) > i) {
        float4 bi = sBox[i];
        float  ai = sArea[i];
        #pragma unroll 8
        for (int b = 0; b < 64; b++) {
            int j = j0 + b;
            float4 bj = sBox[j];
            float  aj = sArea[j];
            float iy = fmaxf(0.0f, fminf(bi.z, bj.z) - fmaxf(bi.x, bj.x));
            float ix = fmaxf(0.0f, fminf(bi.w, bj.w) - fmaxf(bi.y, bj.y));
            float inter = iy * ix;
            float iou = inter / (ai + aj - inter + 1e-9f);
            if (iou > IOU_THR && j > i) word |= (1ull << b);
        }
    }
    g_mask1024[i * MWORDS + w] = word;
}

// ---------------- K5b: single-warp bit-scan NMS + parallel write-out ----------------
// dynamic smem: mask 128KB + 1024 boxes 16KB = 147456 B
__global__ void k5b_scan(float* __restrict__ out) {
    extern __shared__ char sm[];
    u64*    smMask = (u64*)sm;                                 // MCH*MWORDS
    float4* sBox   = (float4*)(sm + MCH * MWORDS * sizeof(u64)); // MCH
    __shared__ u32    sKeptIdx[POST_NMS + 8];
    __shared__ int    sKept;
    __shared__ float4 kb[POST_NMS + 8];
    __shared__ float  karea[POST_NMS + 8];

    int t = threadIdx.x;   // 256
    int n = min((int)g_candCount, PRE_NMS);
    int m = min(n, MCH);

    // stage mask + boxes
    {
        const float4* gm = (const float4*)g_mask1024;
        float4* dm = (float4*)smMask;
        for (int k = t; k < MCH * MWORDS / 2; k += 256) dm[k] = gm[k];
        for (int j = t; j < m; j += 256) sBox[j] = g_sortedBoxes[j];
    }
    __syncthreads();

    // serial bit-scan by warp 0: lane l holds removed word l (l<16)
    if (t < 32) {
        u64 rem = 0ull;
        int kept = 0;
        for (int i = 0; i < m; i++) {
            u32 bit = (u32)((rem >> (i & 63)) & 1ull);
            u32 sbit = __shfl_sync(0xffffffffu, bit, i >> 6);
            if (!sbit) {
                if (t < MWORDS) rem |= smMask[i * MWORDS + t];
                if (t == 0) sKeptIdx[kept] = (u32)i;
                kept++;
                if (kept >= POST_NMS) break;
            }
        }
        if (t == 0) sKept = kept;
    }
    __syncthreads();
    int kept = sKept;

    // parallel write-out of kept boxes
    for (int k = t; k < kept; k += 256)
        reinterpret_cast<float4*>(out)[k] = sBox[sKeptIdx[k]];

    // -------- fallback (rare): not enough keeps within first MCH candidates --------
    if (kept < POST_NMS && n > m) {
        for (int k = t; k < kept; k += 256) {
            float4 b = sBox[sKeptIdx[k]];
            kb[k] = b;
            karea[k] = (b.z - b.x) * (b.w - b.y);
        }
        __syncthreads();
        // reuse mask smem as box buffer for candidates m..n-1 (capacity 8192)
        float4* xBox = (float4*)smMask;
        for (int j = t; j < n - m; j += 256) xBox[j] = g_sortedBoxes[m + j];
        __syncthreads();
        for (int i = 0; i < n - m; i++) {
            float4 b = xBox[i];
            float  ab = (b.z - b.x) * (b.w - b.y);
            bool sup = false;
            for (int k = t; k < kept; k += 256) {
                float4 c  = kb[k];
                float  ac = karea[k];
                float iy = fmaxf(0.0f, fminf(b.z, c.z) - fmaxf(b.x, c.x));
                float ix = fmaxf(0.0f, fminf(b.w, c.w) - fmaxf(b.y, c.y));
                float inter = iy * ix;
                float iou = inter / (ab + ac - inter + 1e-9f);
                sup = sup || (iou > IOU_THR);
            }
            int any = __syncthreads_or((int)sup);
            if (!any) {
                if (t == 0) {
                    kb[kept]    = b;
                    karea[kept] = ab;
                    reinterpret_cast<float4*>(out)[kept] = b;
                }
                kept++;
                if (kept >= POST_NMS) break;
                __syncthreads();
            }
        }
    }
}

// ---------------- launch ----------------
extern "C" void kernel_launch(void* const* d_in, const int* in_sizes, int n_in,
                              void* d_out, int out_size) {
    const float* deltas  = (const float*)d_in[0];
    const float* anchors = (const float*)d_in[1];
    const float* scores  = (const float*)d_in[2];
    int N = in_sizes[2];
    if (N > NMAX) N = NMAX;
    float* out = (float*)d_out;

    k0_zero<<<256, 256>>>(out);
    k1_decode<<<(N + 255) / 256, 256>>>(deltas, anchors, scores, N);
    k2_threshold<<<1, 1024>>>();
    k3_compact<<<(N + 255) / 256, 256>>>(N);
    k4_rank<<<CAP / 256, 256>>>();
    k5a_mask<<<MCH / 16, 256>>>();
    static const int SMEM5B = MCH * MWORDS * (int)sizeof(u64) + MCH * (int)sizeof(float4);
    cudaFuncSetAttribute(k5b_scan, cudaFuncAttributeMaxDynamicSharedMemorySize, SMEM5B);
    k5b_scan<<<1, 256, SMEM5B>>>(out);
}

// round 4
// speedup vs baseline: 3.7145x; 1.3086x over previous
#include <cuda_runtime.h>
#include <cstdint>

typedef unsigned long long u64;
typedef unsigned int u32;

#define NMAX      250048
#define PRE_NMS   6000
#define POST_NMS  300
#define CAP       32768
#define SEGS      8
#define IOU_THR   0.7f
#define IMG_H     1024.0f
#define IMG_W     1024.0f
#define STRIDE_F  16.0f
#define MCH       1024          // fast-path chunk for NMS bitmask
#define MWORDS    16            // 1024/64

// ---------------- device scratch (static, allocation-free) ----------------
__device__ u32    g_hist[65536];
__device__ u32    g_t16;
__device__ u32    g_candCount;
__device__ u32    g_score32[NMAX];      // flipped score, 0 = invalid
__device__ u64    g_cand[CAP];
__device__ u32    g_rank[CAP];
__device__ float4 g_sortedBoxes[PRE_NMS + 64];
__device__ __align__(16) u64 g_mask1024[MCH * MWORDS];

// ---------------- helpers ----------------
__device__ __forceinline__ u32 flip_score(float s) {
    u32 u = __float_as_uint(s);
    return (u & 0x80000000u) ? ~u : (u | 0x80000000u);
}

// decode anchor idx -> clipped box (exact same fp ops in k1 and k4b)
__device__ __forceinline__ float4 decode_box(const float* __restrict__ deltas,
                                             const float* __restrict__ anchors,
                                             int i) {
    float4 a = reinterpret_cast<const float4*>(anchors)[i];
    float4 d = reinterpret_cast<const float4*>(deltas)[i];
    float h = a.z - a.x;
    float w = a.w - a.y;
    float cy = a.x + 0.5f * h;
    float cx = a.y + 0.5f * w;
    float ncy = d.x * h + cy;
    float ncx = d.y * w + cx;
    float nh = expf(d.z) * h;
    float nw = expf(d.w) * w;
    float ymin = fminf(fmaxf(ncy - 0.5f * nh, 0.0f), IMG_H);
    float xmin = fminf(fmaxf(ncx - 0.5f * nw, 0.0f), IMG_W);
    float ymax = fminf(fmaxf(ncy + 0.5f * nh, 0.0f), IMG_H);
    float xmax = fminf(fmaxf(ncx + 0.5f * nw, 0.0f), IMG_W);
    return make_float4(ymin, xmin, ymax, xmax);
}

// ---------------- K0: zero scratch + output ----------------
__global__ void k0_zero(float* out) {
    int i = blockIdx.x * 256 + threadIdx.x;
    if (i < 65536) g_hist[i] = 0u;
    if (i < CAP) g_rank[i] = 0u;
    if (i < POST_NMS * 4) out[i] = 0.0f;
    if (i == 0) g_candCount = 0u;
}

// ---------------- K1: decode + valid + flipped score + 16-bit histogram ----------------
__global__ void k1_decode(const float* __restrict__ deltas,
                          const float* __restrict__ anchors,
                          const float* __restrict__ scores, int N) {
    int i = blockIdx.x * 256 + threadIdx.x;
    if (i >= N) return;
    float4 b = decode_box(deltas, anchors, i);
    bool valid = ((b.z - b.x) >= STRIDE_F) && ((b.w - b.y) >= STRIDE_F);
    u32 s = 0u;
    if (valid) {
        s = flip_score(scores[i]);
        atomicAdd(&g_hist[s >> 16], 1u);
    }
    g_score32[i] = s;
}

// ---------------- K2: find 16-bit threshold so that count(prefix >= t) >= 6000 ----------------
__global__ void k2_threshold() {
    __shared__ u32 ssum[1024];
    int t = threadIdx.x;
    u32 sum = 0;
    #pragma unroll 8
    for (int b = 0; b < 64; b++) sum += g_hist[(t << 6) + b];
    ssum[t] = sum;
    __syncthreads();
    for (int off = 1; off < 1024; off <<= 1) {
        u32 v = (t + off < 1024) ? ssum[t + off] : 0u;
        __syncthreads();
        ssum[t] += v;
        __syncthreads();
    }
    u32 myCum = ssum[t];
    u32 nxtCum = (t < 1023) ? ssum[t + 1] : 0u;
    if (myCum >= PRE_NMS && nxtCum < PRE_NMS) {
        u32 running = nxtCum;
        for (int b = 63; b >= 0; b--) {
            running += g_hist[(t << 6) + b];
            if (running >= PRE_NMS) { g_t16 = (u32)((t << 6) + b); break; }
        }
    }
    if (t == 0 && ssum[0] < PRE_NMS) g_t16 = 0u;
}

// ---------------- K3: compact candidates, block-aggregated atomics ----------------
__global__ void k3_compact(int N) {
    __shared__ u32 sCnt;
    __shared__ u32 sBase;
    int t = threadIdx.x;
    if (t == 0) sCnt = 0u;
    __syncthreads();
    int i = blockIdx.x * 256 + t;
    u32 s = (i < N) ? g_score32[i] : 0u;
    bool pass = (s != 0u) && ((s >> 16) >= g_t16);
    u32 local = 0u;
    if (pass) local = atomicAdd(&sCnt, 1u);
    __syncthreads();
    if (t == 0) sBase = (sCnt > 0u) ? atomicAdd(&g_candCount, sCnt) : 0u;
    __syncthreads();
    if (pass) {
        u32 pos = sBase + local;
        if (pos < CAP) g_cand[pos] = ((u64)s << 32) | (u32)(~(u32)i);
    }
}

// ---------------- K4a: partial rank counts (8-way column split) ----------------
__global__ void k4a_count() {
    int C = min((int)g_candCount, CAP);
    int rowBase = blockIdx.x * 256;
    if (rowBase >= C) return;
    int segLen = (C + SEGS - 1) / SEGS;
    int c0 = blockIdx.y * segLen;
    if (c0 >= C) return;
    int c1 = min(c0 + segLen, C);
    int t = threadIdx.x;
    int row = rowBase + t;
    u64 myKey = (row < C) ? g_cand[row] : 0ull;
    __shared__ u64 tile[256];
    int cnt = 0;
    for (int base = c0; base < c1; base += 256) {
        int idx = base + t;
        if (idx < c1) tile[t] = g_cand[idx];
        __syncthreads();
        int m = min(256, c1 - base);
        int k = 0;
        for (; k + 4 <= m; k += 4) {
            cnt += (tile[k]   > myKey);
            cnt += (tile[k+1] > myKey);
            cnt += (tile[k+2] > myKey);
            cnt += (tile[k+3] > myKey);
        }
        for (; k < m; k++) cnt += (tile[k] > myKey);
        __syncthreads();
    }
    if (row < C && cnt > 0) atomicAdd(&g_rank[row], (u32)cnt);
}

// ---------------- K4b: scatter — recompute decode for candidates only ----------------
__global__ void k4b_scatter(const float* __restrict__ deltas,
                            const float* __restrict__ anchors) {
    int C = min((int)g_candCount, CAP);
    int i = blockIdx.x * 256 + threadIdx.x;
    if (i >= C) return;
    u32 rank = g_rank[i];
    if (rank >= PRE_NMS) return;
    u64 key = g_cand[i];
    int idx = (int)(~(u32)(key & 0xFFFFFFFFull));
    g_sortedBoxes[rank] = decode_box(deltas, anchors, idx);
}

// ---------------- K5a: suppression bitmask over first 1024 candidates ----------------
__global__ void k5a_mask() {
    __shared__ float4 sBox[MCH];
    __shared__ float  sArea[MCH];
    int n = min((int)g_candCount, PRE_NMS);
    for (int j = threadIdx.x; j < MCH; j += 256) {
        float4 b = (j < n) ? g_sortedBoxes[j] : make_float4(0.f, 0.f, 0.f, 0.f);
        sBox[j] = b;
        sArea[j] = (b.z - b.x) * (b.w - b.y);
    }
    __syncthreads();
    int r = threadIdx.x & 15;
    int w = threadIdx.x >> 4;
    int i = blockIdx.x * 16 + r;
    u64 word = 0ull;
    int j0 = w << 6;
    if (i < n && (j0 + 63) > i) {
        float4 bi = sBox[i];
        float  ai = sArea[i];
        #pragma unroll 8
        for (int b = 0; b < 64; b++) {
            int j = j0 + b;
            float4 bj = sBox[j];
            float  aj = sArea[j];
            float iy = fmaxf(0.0f, fminf(bi.z, bj.z) - fmaxf(bi.x, bj.x));
            float ix = fmaxf(0.0f, fminf(bi.w, bj.w) - fmaxf(bi.y, bj.y));
            float inter = iy * ix;
            float iou = inter / (ai + aj - inter + 1e-9f);
            if (iou > IOU_THR && j > i) word |= (1ull << b);
        }
    }
    g_mask1024[i * MWORDS + w] = word;
}

// ---------------- K5b: single-warp bit-scan NMS + parallel write-out ----------------
// dynamic smem: mask 128KB
__global__ void k5b_scan(float* __restrict__ out) {
    extern __shared__ char sm[];
    u64* smMask = (u64*)sm;                                  // MCH*MWORDS
    __shared__ u32    sKeptIdx[POST_NMS + 8];
    __shared__ int    sKept;
    __shared__ float4 kb[POST_NMS + 8];
    __shared__ float  karea[POST_NMS + 8];

    int t = threadIdx.x;   // 256
    int n = min((int)g_candCount, PRE_NMS);
    int m = min(n, MCH);

    // stage mask
    {
        const float4* gm = (const float4*)g_mask1024;
        float4* dm = (float4*)smMask;
        for (int k = t; k < MCH * MWORDS / 2; k += 256) dm[k] = gm[k];
    }
    __syncthreads();

    // serial bit-scan by warp 0: lane l holds removed word l (l<16)
    if (t < 32) {
        u64 rem = 0ull;
        int kept = 0;
        for (int i = 0; i < m; i++) {
            u32 bit = (u32)((rem >> (i & 63)) & 1ull);
            u32 sbit = __shfl_sync(0xffffffffu, bit, i >> 6);
            if (!sbit) {
                if (t < MWORDS) rem |= smMask[i * MWORDS + t];
                if (t == 0) sKeptIdx[kept] = (u32)i;
                kept++;
                if (kept >= POST_NMS) break;
            }
        }
        if (t == 0) sKept = kept;
    }
    __syncthreads();
    int kept = sKept;

    // parallel write-out of kept boxes
    for (int k = t; k < kept; k += 256)
        reinterpret_cast<float4*>(out)[k] = g_sortedBoxes[sKeptIdx[k]];

    // -------- fallback (rare): not enough keeps within first MCH candidates --------
    if (kept < POST_NMS && n > m) {
        for (int k = t; k < kept; k += 256) {
            float4 b = g_sortedBoxes[sKeptIdx[k]];
            kb[k] = b;
            karea[k] = (b.z - b.x) * (b.w - b.y);
        }
        __syncthreads();
        // reuse mask smem as box buffer for candidates m..n-1 (capacity 8192)
        float4* xBox = (float4*)smMask;
        for (int j = t; j < n - m; j += 256) xBox[j] = g_sortedBoxes[m + j];
        __syncthreads();
        for (int i = 0; i < n - m; i++) {
            float4 b = xBox[i];
            float  ab = (b.z - b.x) * (b.w - b.y);
            bool sup = false;
            for (int k = t; k < kept; k += 256) {
                float4 c  = kb[k];
                float  ac = karea[k];
                float iy = fmaxf(0.0f, fminf(b.z, c.z) - fmaxf(b.x, c.x));
                float ix = fmaxf(0.0f, fminf(b.w, c.w) - fmaxf(b.y, c.y));
                float inter = iy * ix;
                float iou = inter / (ab + ac - inter + 1e-9f);
                sup = sup || (iou > IOU_THR);
            }
            int any = __syncthreads_or((int)sup);
            if (!any) {
                if (t == 0) {
                    kb[kept]    = b;
                    karea[kept] = ab;
                    reinterpret_cast<float4*>(out)[kept] = b;
                }
                kept++;
                if (kept >= POST_NMS) break;
                __syncthreads();
            }
        }
    }
}

// ---------------- launch ----------------
extern "C" void kernel_launch(void* const* d_in, const int* in_sizes, int n_in,
                              void* d_out, int out_size) {
    const float* deltas  = (const float*)d_in[0];
    const float* anchors = (const float*)d_in[1];
    const float* scores  = (const float*)d_in[2];
    int N = in_sizes[2];
    if (N > NMAX) N = NMAX;
    float* out = (float*)d_out;

    k0_zero<<<256, 256>>>(out);
    k1_decode<<<(N + 255) / 256, 256>>>(deltas, anchors, scores, N);
    k2_threshold<<<1, 1024>>>();
    k3_compact<<<(N + 255) / 256, 256>>>(N);
    k4a_count<<<dim3(CAP / 256, SEGS), 256>>>();
    k4b_scatter<<<CAP / 256, 256>>>(deltas, anchors);
    k5a_mask<<<MCH / 16, 256>>>();
    static const int SMEM5B = MCH * MWORDS * (int)sizeof(u64);
    cudaFuncSetAttribute(k5b_scan, cudaFuncAttributeMaxDynamicSharedMemorySize, SMEM5B);
    k5b_scan<<<1, 256, SMEM5B>>>(out);
}